// round 14
// baseline (speedup 1.0000x reference)
#include <cuda_runtime.h>
#include <cuda_bf16.h>
#include <math.h>

// EnhancedPIICRF loss on GB300. B=512, T=4096, L=15; mask all-ones; labels int32.
//
// Linear-domain forward algorithm, parallel-in-time via mixing (C=128 chunks of
// S=32, W=4 warmup, telescoping stitch). bf16x2 HFMA2 matvec.
// R12 regressed because window staging exposed full LDG latency (LDG->STS in
// one block before compute). This version restores the register pipeline:
// window w+1's 15 float4 LDGs issue BEFORE window w's compute, convert+STS
// happen AFTER it. E-matrix columns read as explicit uint4 (2x LDS.128).

#define BB 512
#define TT 4096
#define LL 15
#define CC 128
#define SS 32
#define WW 4
#define BLK 32
#define RS 31              // smem words per row-window (30 bf16x2 + 1 pad)
#define RF4 (TT*LL/4)      // float4 per emission row

__device__ float g_out0[CC][BB];
__device__ float g_u[CC][BB];
__device__ float g_num[CC][BB];
__device__ float g_final[BB][16];
__device__ float g_llh[BB];

__device__ __forceinline__ unsigned pack_bf16x2(float x, float y) {
    __nv_bfloat162 t = __floats2bfloat162_rn(x, y);   // low=x, high=y
    return *(unsigned*)&t;
}
__device__ __forceinline__ float bf_lo(unsigned w) { return __uint_as_float(w << 16); }
__device__ __forceinline__ float bf_hi(unsigned w) { return __uint_as_float(w & 0xffff0000u); }

__global__ __launch_bounds__(BLK, 14)
void crf_scan(const float* __restrict__ em,
              const float* __restrict__ trans,
              const float* __restrict__ startT,
              const int* __restrict__ labels)
{
    __shared__ __align__(16) __nv_bfloat162 sEh[LL][8];  // exp(T) i-pairs per column
    __shared__ float sLT[LL * 16];                       // raw transitions (numerator)
    __shared__ int sLab[BLK][33];                        // labels, main window
    __shared__ unsigned sW[2][BLK * RS];                 // bf16 emission windows

    const int tid = threadIdx.x;
    for (int x = tid; x < 120; x += BLK) {
        int j = x >> 3, p = x & 7;
        float e0 = expf(trans[(2 * p) * LL + j]);                       // exp(-10000)=0
        float e1 = (2 * p + 1 < LL) ? expf(trans[(2 * p + 1) * LL + j]) : 0.0f;
        sEh[j][p] = __halves2bfloat162(__float2bfloat16(e0), __float2bfloat16(e1));
    }
    for (int x = tid; x < 240; x += BLK)
        sLT[x] = ((x & 15) < LL) ? trans[(x >> 4) * LL + (x & 15)] : 0.0f;

    const int c  = blockIdx.x >> 4;
    const int b0 = (blockIdx.x & 15) * BLK;
    const int b  = b0 + tid;

    const int t0   = c * SS;
    const int tA   = (c == 0) ? 0 : t0 - WW;
    const int NW   = (c == 0) ? 8 : 9;       // 4-step windows covering [tA, t0+32)

    const float4* emblk4 = (const float4*)(em + (size_t)b0 * (TT * LL));
    const int     base0  = (tA * 15) >> 2;   // exact: tA*15 % 4 == 0

    // ---- stage labels for [t0, t0+32): coalesced per row ----
    #pragma unroll
    for (int w = 0; w < 8; w++) {
        int n  = w * BLK + tid;
        int r  = n >> 3, i4 = n & 7;
        int4 v = *(const int4*)&labels[(size_t)(b0 + r) * TT + t0 + i4 * 4];
        sLab[r][i4 * 4 + 0] = v.x;
        sLab[r][i4 * 4 + 1] = v.y;
        sLab[r][i4 * 4 + 2] = v.z;
        sLab[r][i4 * 4 + 3] = v.w;
    }

    // cooperative (row, float4) pairs: element e = k*32 + tid -> rr=e/15, qq=e%15
    int rq[15];
    {
        int rv = (tid >= 30) ? 2 : (tid >= 15 ? 1 : 0);
        int qv = tid - rv * 15;
        #pragma unroll
        for (int k = 0; k < 15; k++) {
            rq[k] = (rv << 8) | qv;
            rv += 2; qv += 2;
            if (qv >= 15) { qv -= 15; rv += 1; }
        }
    }

    // ---- stage window 0 synchronously (one-time latency exposure) ----
    {
        #pragma unroll
        for (int k = 0; k < 15; k++) {
            int r = rq[k] >> 8, q = rq[k] & 255;
            float4 v = emblk4[r * RF4 + base0 + q];
            int a = r * RS + 2 * q;
            sW[0][a]     = pack_bf16x2(v.x, v.y);
            sW[0][a + 1] = pack_bf16x2(v.z, v.w);
        }
    }
    __syncwarp();

    // ---- init alpha at t = tA (window 0, slot 0) ----
    __nv_bfloat162 ap[8];
    {
        const unsigned* buf0 = &sW[0][tid * RS];
        float av[15];
        #pragma unroll
        for (int j = 0; j < LL; j++) {
            unsigned wv = buf0[j >> 1];
            float v = (j & 1) ? bf_hi(wv) : bf_lo(wv);
            if (c == 0) v += startT[j];
            av[j] = __expf(v);
        }
        #pragma unroll
        for (int p = 0; p < 7; p++)
            ap[p] = __floats2bfloat162_rn(av[2 * p], av[2 * p + 1]);
        ap[7] = __floats2bfloat162_rn(av[14], 0.0f);
    }
    float logscale = 0.0f, num = 0.0f;
    int labPrev;
    if (c == 0) {
        labPrev = sLab[tid][0];
        const unsigned* buf0 = &sW[0][tid * RS];
        unsigned wv = buf0[labPrev >> 1];
        num = startT[labPrev] + ((labPrev & 1) ? bf_hi(wv) : bf_lo(wv));
    } else {
        labPrev = labels[(size_t)b * TT + t0 - 1];
    }

    #pragma unroll 1
    for (int w = 0; w < NW; ++w) {
        // issue next window's loads FIRST; consume (convert+STS) after compute
        float4 V[15];
        const bool hasNext = (w + 1 < NW);
        if (hasNext) {
            const int basef = base0 + 15 * (w + 1);
            #pragma unroll
            for (int k = 0; k < 15; k++) {
                int r = rq[k] >> 8, q = rq[k] & 255;
                V[k] = emblk4[r * RF4 + basef + q];
            }
        }

        const unsigned* buf = &sW[w & 1][tid * RS];
        const int tw = tA + 4 * w;

        #pragma unroll
        for (int s = 0; s < 4; ++s) {
            if (w == 0 && s == 0) continue;            // init slot
            const int tcur = tw + s;
            const int ws = (15 * s) >> 1;              // 0,7,15,22 (compile-time)
            unsigned Wd[8];
            #pragma unroll
            for (int m = 0; m < 8; m++) Wd[m] = buf[ws + m];

            float ex[15];
            #pragma unroll
            for (int j = 0; j < LL; j++) {
                int ib = (s & 1) + j;                  // compile-time parity
                unsigned wv = Wd[ib >> 1];
                ex[j] = (ib & 1) ? bf_hi(wv) : bf_lo(wv);
            }

            if (tcur >= t0) {                          // numerator
                int labt = sLab[tid][tcur - t0];
                int ib = 15 * s + labt;
                unsigned wv = buf[ib >> 1];
                float emlab = (ib & 1) ? bf_hi(wv) : bf_lo(wv);
                num += emlab + sLT[labPrev * 16 + labt];
                labPrev = labt;
            }

            __nv_bfloat162 ep[8];
            #pragma unroll
            for (int p = 0; p < 7; p++)
                ep[p] = __floats2bfloat162_rn(__expf(ex[2 * p]), __expf(ex[2 * p + 1]));
            ep[7] = __floats2bfloat162_rn(__expf(ex[14]), 0.0f);

            // matvec: acc[j] = sum_p ap[p] .* E2[j][p]; E column via 2x LDS.128
            __nv_bfloat162 acc[15];
            #pragma unroll
            for (int j = 0; j < LL; j++) {
                const uint4* colv = (const uint4*)&sEh[j][0];
                uint4 c0 = colv[0], c1 = colv[1];
                __nv_bfloat162 t2;
                t2 = __hmul2(ap[0], *(__nv_bfloat162*)&c0.x);
                t2 = __hfma2(ap[1], *(__nv_bfloat162*)&c0.y, t2);
                t2 = __hfma2(ap[2], *(__nv_bfloat162*)&c0.z, t2);
                t2 = __hfma2(ap[3], *(__nv_bfloat162*)&c0.w, t2);
                t2 = __hfma2(ap[4], *(__nv_bfloat162*)&c1.x, t2);
                t2 = __hfma2(ap[5], *(__nv_bfloat162*)&c1.y, t2);
                t2 = __hfma2(ap[6], *(__nv_bfloat162*)&c1.z, t2);
                t2 = __hfma2(ap[7], *(__nv_bfloat162*)&c1.w, t2);
                acc[j] = t2;
            }
            #pragma unroll
            for (int p = 0; p < 7; p++) {
                __nv_bfloat162 A = acc[2 * p], B = acc[2 * p + 1];
                __nv_bfloat162 lo = __halves2bfloat162(__low2bfloat16(A),  __low2bfloat16(B));
                __nv_bfloat162 hi = __halves2bfloat162(__high2bfloat16(A), __high2bfloat16(B));
                ap[p] = __hmul2(__hadd2(lo, hi), ep[p]);
            }
            {
                __nv_bfloat16 s14 = __hadd(__low2bfloat16(acc[14]), __high2bfloat16(acc[14]));
                ap[7] = __hmul2(__halves2bfloat162(s14, __float2bfloat16(0.0f)), ep[7]);
            }

            if ((tcur & 7) == 7) {                      // renorm
                __nv_bfloat162 mx = ap[0];
                #pragma unroll
                for (int p = 1; p < 8; p++) mx = __hmax2(mx, ap[p]);
                float m = fmaxf(__low2float(mx), __high2float(mx));
                logscale += __logf(m);
                __nv_bfloat162 r2 = __float2bfloat162_rn(__fdividef(1.0f, m));
                #pragma unroll
                for (int p = 0; p < 8; p++) ap[p] = __hmul2(ap[p], r2);
            }

            if (c > 0 && tcur == t0 - 1)
                g_u[c][b] = __logf(__low2float(ap[0])) + logscale;
        }

        // convert + store next window AFTER compute (loads now long complete)
        if (hasNext) {
            unsigned* dst = sW[(w + 1) & 1];
            #pragma unroll
            for (int k = 0; k < 15; k++) {
                int r = rq[k] >> 8, q = rq[k] & 255;
                int a = r * RS + 2 * q;
                dst[a]     = pack_bf16x2(V[k].x, V[k].y);
                dst[a + 1] = pack_bf16x2(V[k].z, V[k].w);
            }
        }
        __syncwarp();
    }

    g_out0[c][b] = __logf(__low2float(ap[0])) + logscale;
    g_num[c][b]  = num;
    if (c == CC - 1) {
        #pragma unroll
        for (int p = 0; p < 7; p++) {
            g_final[b][2 * p]     = __low2float(ap[p]);
            g_final[b][2 * p + 1] = __high2float(ap[p]);
        }
        g_final[b][14] = __low2float(ap[7]);   // linear-domain; combined in fin1
    }
}

// grid = 512 (one block per b), 32 threads (c strided)
__global__ __launch_bounds__(32)
void crf_fin1(const float* __restrict__ endT,
              const int* __restrict__ labels)
{
    int b = blockIdx.x, ct = threadIdx.x;
    float v = 0.0f;
    #pragma unroll
    for (int c = ct; c < CC; c += 32) {
        float x = g_num[c][b];
        if (c < CC - 1) x -= g_out0[c][b];
        if (c > 0)      x += g_u[c][b];
        v += x;
    }
    #pragma unroll
    for (int o = 16; o > 0; o >>= 1) v += __shfl_xor_sync(0xffffffffu, v, o);
    if (ct == 0) {
        // lse = g_out0[CC-1] - log(a0) + log(sum_j a_j e^{endT_j})
        float a0 = g_final[b][0];
        float se = 0.0f;
        #pragma unroll
        for (int j = 0; j < LL; j++) se += g_final[b][j] * __expf(endT[j]);
        float lse = g_out0[CC - 1][b] - __logf(a0) + __logf(se);
        g_llh[b] = v + endT[labels[(size_t)b * TT + (TT - 1)]] - lse;
    }
}

__global__ __launch_bounds__(512)
void crf_fin2(float* __restrict__ out)
{
    __shared__ float red[512];
    int i = threadIdx.x;
    red[i] = g_llh[i];
    __syncthreads();
    for (int o = 256; o > 0; o >>= 1) {
        if (i < o) red[i] += red[i + o];
        __syncthreads();
    }
    if (i == 0) out[0] = -red[0] / (float)BB;
}

extern "C" void kernel_launch(void* const* d_in, const int* in_sizes, int n_in,
                              void* d_out, int out_size)
{
    const float* em     = (const float*)d_in[0];
    const float* trans  = (const float*)d_in[1];
    const float* startT = (const float*)d_in[2];
    const float* endT   = (const float*)d_in[3];
    const int*   labels = (const int*)d_in[4];
    (void)in_sizes; (void)n_in; (void)out_size;

    crf_scan<<<(BB / BLK) * CC, BLK>>>(em, trans, startT, labels);
    crf_fin1<<<BB, 32>>>(endT, labels);
    crf_fin2<<<1, 512>>>((float*)d_out);
}